// round 14
// baseline (speedup 1.0000x reference)
#include <cuda_runtime.h>

// Problem constants (UP=3, DOWN=2, Lh=63, Lb=51)
#define R_OUT 8                    // same-phase outputs per thread
#define BLOCK_T 384                // 3 phase groups x 128 threads
#define OUT_PER_TILE 3072          // 3 * 128 * R_OUT
#define TILE_X 2112                // logical floats per tile (need 2106, even)
#define XS_PHYS 2376               // >= XP(TILE_X-1)+1, 8B aligned
#define OS_GRP 800                 // per lane-group staging slice (768 + pad)
#define NSTEP 29                   // packed coefficient steps (v in [2,60))
#define NB 444                     // persistent blocks = 148 SMs * 3 CTAs

// xs swizzle: pad TWO floats per 16 -> lane logical stride 16 becomes phys
// stride 18 (9*l mod 16 pair-banks, gcd(9,16)=1 -> LDS.64 conflict-free),
// 8B alignment preserved. Window base 16*l: XP(16l + e) = 18l + XPOFF(e).
#define XP(i)    ((i) + (((i) >> 4) << 1))
#define XPOFF(e) ((e) + (((e) >> 4) << 1))

__device__ __forceinline__ unsigned long long fma_f32x2(
    unsigned long long a, unsigned long long bb, unsigned long long c) {
    unsigned long long d;
    asm("fma.rn.f32x2 %0, %1, %2, %3;" : "=l"(d) : "l"(a), "l"(bb), "l"(c));
    return d;
}

// Exact two-stage value for edge outputs (head j<50 where u-padding matters,
// tail j>=n_out where appended zeros matter).
__device__ float edge_value(const float* __restrict__ x,
                            const float* __restrict__ h,
                            const float* __restrict__ b,
                            long long j, int n_in, long long n_out) {
    float acc = 0.0f;
    for (int s = 0; s < 51; s++) {
        long long k = j - s;
        if (k < 0 || k >= n_out) continue;
        long long mlo = (2 * k - 30 + 2) / 3;
        if (mlo < 0) mlo = 0;
        long long mhi = (2 * k + 32) / 3;
        if (mhi > (long long)n_in - 1) mhi = (long long)n_in - 1;
        float u = 0.0f;
        for (long long m = mlo; m <= mhi; m++) {
            long long hi = 2 * k + 32 - 3 * m;
            if (hi >= 0 && hi < 63) u = fmaf(x[m], h[hi], u);
        }
        acc = fmaf(b[s], u, acc);
    }
    return acc;
}

// Tile fill: cp.async (interior) or guarded direct stores (first/last tile).
// Caller commits the group afterwards.
__device__ __forceinline__ void fill_tile(
    float* xs, const float* __restrict__ x,
    int tile, int ntiles, int n_in, int tid)
{
    int G0 = 2048 * tile - 46;     // even; global x index of logical xs[0]
    if (tile != 0 && tile != ntiles - 1) {
        const float2* src = (const float2*)(x + G0);
        #pragma unroll
        for (int q2 = tid; q2 < TILE_X / 2; q2 += BLOCK_T) {
            unsigned dst = (unsigned)__cvta_generic_to_shared(&xs[XP(2 * q2)]);
            asm volatile("cp.async.ca.shared.global [%0], [%1], 8;\n"
                         :: "r"(dst), "l"(src + q2));
        }
    } else {
        #pragma unroll
        for (int q2 = tid; q2 < TILE_X / 2; q2 += BLOCK_T) {
            int i0 = G0 + 2 * q2;
            float2 v;
            v.x = (i0 >= 0 && i0 < n_in) ? x[i0] : 0.0f;
            v.y = (i0 + 1 >= 0 && i0 + 1 < n_in) ? x[i0 + 1] : 0.0f;
            *(float2*)&xs[XP(2 * q2)] = v;
        }
    }
}

// Persistent fused kernel, double-buffered tiles.
// out[j] = sum_m x[m]*C[2j+32-3m], C[r] = sum_s b[s]*h[r-2s] (r in [0,163)).
// Per tile: j = jbase + g + 3*(8*l + d), G0 = 2048*tile - 46 (even).
// With i = 16l + 2d + v: out = sum_v xs_log[16l+2d+v] * D_g[v],
// D_g[v] = C[2g + 170 - 3v] (zero outside [0,162]); nonzero v in [3,59].
__global__ void __launch_bounds__(BLOCK_T, 3) fused_kernel(
    const float* __restrict__ x, const float* __restrict__ h,
    const float* __restrict__ b, float* __restrict__ out,
    int n_in, int n_out, int out_total, int ntiles)
{
    __shared__ float xsb[2][XS_PHYS];
    __shared__ float os[4 * OS_GRP];
    __shared__ unsigned long long cs[3][NSTEP];

    int tid = threadIdx.x;
    int bx = blockIdx.x;
    int nb = gridDim.x;

    // --- prefetch this block's first tile immediately ---
    int tile = bx;
    if (tile < ntiles) fill_tile(xsb[0], x, tile, ntiles, n_in, tid);
    asm volatile("cp.async.commit_group;\n" ::: "memory");

    // --- coefficients: ONCE per persistent block ---
    // cs[g][t] = (D_g[2+2t], D_g[3+2t]) = (C[2g+164-6t], C[2g+161-6t])
    if (tid < 3 * NSTEP) {
        int gg = tid / NSTEP, t = tid % NSTEP;
        float hv[2];
        #pragma unroll
        for (int qq = 0; qq < 2; qq++) {
            int idx = 2 * gg + 164 - 6 * t - 3 * qq;   // C index
            float val = 0.0f;
            if (idx >= 0 && idx <= 162) {
                #pragma unroll
                for (int s = 0; s < 51; s++) {
                    int hh = idx - 2 * s;
                    if (hh >= 0 && hh < 63) val = fmaf(__ldg(&b[s]), __ldg(&h[hh]), val);
                }
            }
            hv[qq] = val;
        }
        cs[gg][t] =
            (unsigned long long)__float_as_uint(hv[0]) |
            ((unsigned long long)__float_as_uint(hv[1]) << 32);
    }

    int g = tid >> 7;
    int l = tid & 127;
    int w = l >> 5;                 // lane-group 0..3
    int ll = l & 31;
    int tt = (g << 5) + ll;         // group-internal index [0,96)
    const unsigned long long* cp_ = cs[g];
    const float* xw = (const float*)0;
    float* og = os + OS_GRP * w;

    int cur = 0;
    for (; tile < ntiles; tile += nb, cur ^= 1) {
        // prefetch next tile into the spare buffer (freed by the post-FIR
        // __syncthreads of the previous iteration)
        int nxt = tile + nb;
        if (nxt < ntiles) fill_tile(xsb[cur ^ 1], x, nxt, ntiles, n_in, tid);
        asm volatile("cp.async.commit_group;\n" ::: "memory");
        asm volatile("cp.async.wait_group 1;\n" ::: "memory");  // this tile ready
        __syncthreads();

        const float* xb = xsb[cur] + 18 * l;

        // circular packed window: slot k = {xs_log[16l+2+2k], xs_log[16l+3+2k]}
        unsigned long long w2[8];
        #pragma unroll
        for (int k = 0; k < 8; k++)
            w2[k] = *(const unsigned long long*)&xb[XPOFF(2 + 2 * k)];

        unsigned long long acc2[R_OUT];
        #pragma unroll
        for (int d = 0; d < R_OUT; d++) acc2[d] = 0ull;

        #pragma unroll
        for (int t = 0; t < NSTEP; t++) {
            unsigned long long c = cp_[t];
            #pragma unroll
            for (int d = 0; d < R_OUT; d++)
                acc2[d] = fma_f32x2(w2[(t + d) & 7], c, acc2[d]);
            if (t < NSTEP - 1)
                w2[t & 7] = *(const unsigned long long*)&xb[XPOFF(2 + 2 * (t + 8))];
        }
        __syncthreads();   // all reads of xsb[cur] done -> safe to prefetch into it next iter

        // --- group-local staging: logical oo = g + 3*(8*ll + d) = 24*ll + (g+3d),
        //     phys = oo + oo/24 = 25*ll + g + 3*d (stride 25: conflict-free) ---
        #pragma unroll
        for (int d = 0; d < R_OUT; d++) {
            float lo = __uint_as_float((unsigned)(acc2[d] & 0xffffffffull));
            float hi = __uint_as_float((unsigned)(acc2[d] >> 32));
            og[25 * ll + g + 3 * d] = lo + hi;
        }
        // 3-warp rendezvous: warps {w, w+4, w+8} (96 threads), barrier id w+1
        asm volatile("bar.sync %0, 96;" :: "r"(w + 1) : "memory");

        // --- group-local coalesced writeback (group covers 768 outputs) ---
        int jgrp = tile * OUT_PER_TILE + 768 * w;
        if (jgrp >= 50 && jgrp + 768 <= n_out) {
            #pragma unroll
            for (int it = 0; it < 2; it++) {
                int q4 = 4 * tt + 384 * it;
                int ph = q4 + q4 / 24;
                float4 v;
                v.x = og[ph];
                v.y = og[ph + 1];
                v.z = og[ph + 2];
                v.w = og[ph + 3];
                *(float4*)&out[jgrp + q4] = v;
            }
        } else {
            for (int q = tt; q < 768; q += 96) {
                int j = jgrp + q;
                // j >= 50 (head handled exactly below) and j < n_out
                if ((unsigned)(j - 50) < (unsigned)(n_out - 50)) out[j] = og[q + q / 24];
            }
        }
    }

    // --- block 0: exact edge outputs (head + tail) ---
    if (bx == 0) {
        int n_tail = out_total - n_out;
        if (tid < 50 + n_tail) {
            long long j = (tid < 50) ? (long long)tid
                                     : (long long)n_out + (tid - 50);
            out[j] = edge_value(x, h, b, j, n_in, (long long)n_out);
        }
    }
}

extern "C" void kernel_launch(void* const* d_in, const int* in_sizes, int n_in_arrs,
                              void* d_out, int out_size) {
    const float* x = (const float*)d_in[0];
    const float* h = (const float*)d_in[1];
    const float* b = (const float*)d_in[2];
    float* out = (float*)d_out;

    int n_in = in_sizes[0];  // 8 * 1048576 = 8388608
    long long n3 = (long long)n_in * 3;
    long long n_out = n3 / 2 + ((n3 % 2) ? 1 : 0);  // 12582912
    int out_total = out_size;                        // 12583008
    int ntiles = (int)((n_out + OUT_PER_TILE - 1) / OUT_PER_TILE);  // 4096

    int grid = NB < ntiles ? NB : ntiles;
    fused_kernel<<<grid, BLOCK_T>>>(x, h, b, out, n_in, (int)n_out, out_total, ntiles);
}

// round 15
// speedup vs baseline: 1.0325x; 1.0325x over previous
#include <cuda_runtime.h>

// Problem constants (UP=3, DOWN=2, Lh=63, Lb=51)
#define R_OUT 16                   // same-phase outputs per thread
#define BLOCK_T 384                // 4 independent groups x 96 threads
#define GT_OUT 1536                // outputs per group-tile (3*32*16)
#define TILE_XG 1084               // logical floats per group-tile (need 1082)
#define XS_G 1152                  // phys floats per buffer (XP(1083)=1149, padded)
#define OS_G 1616                  // staging floats per group (49*31+48, padded)
#define NSTEP 29                   // packed coefficient steps (v in [2,60))
#define NBLK 296                   // persistent blocks = 148 SMs * 2 CTAs

// smem layout (dynamic, floats):
// [0, 8*XS_G)            xs buffers: group a, buf c at (2a+c)*XS_G
// [8*XS_G, +4*OS_G)      os staging slices
// then cs: 3*NSTEP u64
#define SMEM_FLOATS (8 * XS_G + 4 * OS_G)
#define SMEM_BYTES  (SMEM_FLOATS * 4 + 3 * NSTEP * 8)

// xs swizzle: pad TWO floats per 32 -> lane logical stride 32 becomes phys
// stride 34 (LDS.64 conflict-free), 8B alignment preserved.
// Window base 32*ll: XP(32*ll + e) = 34*ll + XPOFF(e).
#define XP(i)    ((i) + (((i) >> 5) << 1))
#define XPOFF(e) ((e) + (((e) >> 5) << 1))

__device__ __forceinline__ unsigned long long fma_f32x2(
    unsigned long long a, unsigned long long bb, unsigned long long c) {
    unsigned long long d;
    asm("fma.rn.f32x2 %0, %1, %2, %3;" : "=l"(d) : "l"(a), "l"(bb), "l"(c));
    return d;
}

// Exact two-stage value for edge outputs (head j<50 where u-padding matters,
// tail j>=n_out where appended zeros matter).
__device__ float edge_value(const float* __restrict__ x,
                            const float* __restrict__ h,
                            const float* __restrict__ b,
                            long long j, int n_in, long long n_out) {
    float acc = 0.0f;
    for (int s = 0; s < 51; s++) {
        long long k = j - s;
        if (k < 0 || k >= n_out) continue;
        long long mlo = (2 * k - 30 + 2) / 3;
        if (mlo < 0) mlo = 0;
        long long mhi = (2 * k + 32) / 3;
        if (mhi > (long long)n_in - 1) mhi = (long long)n_in - 1;
        float u = 0.0f;
        for (long long m = mlo; m <= mhi; m++) {
            long long hi = 2 * k + 32 - 3 * m;
            if (hi >= 0 && hi < 63) u = fmaf(x[m], h[hi], u);
        }
        acc = fmaf(b[s], u, acc);
    }
    return acc;
}

// Group-tile fill: cp.async (interior) or guarded stores (first/last tile).
// Caller commits the group.
__device__ __forceinline__ void fill_g(
    float* xs, const float* __restrict__ x,
    int T, int ntiles, int n_in, int t96)
{
    int G0 = (T << 10) - 46;       // even; global x index of logical xs[0]
    if (T != 0 && T != ntiles - 1) {
        const float2* src = (const float2*)(x + G0);
        #pragma unroll
        for (int q2 = t96; q2 < TILE_XG / 2; q2 += 96) {
            unsigned dst = (unsigned)__cvta_generic_to_shared(&xs[XP(2 * q2)]);
            asm volatile("cp.async.ca.shared.global [%0], [%1], 8;\n"
                         :: "r"(dst), "l"(src + q2));
        }
    } else {
        #pragma unroll
        for (int q2 = t96; q2 < TILE_XG / 2; q2 += 96) {
            int i0 = G0 + 2 * q2;
            float2 v;
            v.x = (i0 >= 0 && i0 < n_in) ? x[i0] : 0.0f;
            v.y = (i0 + 1 >= 0 && i0 + 1 < n_in) ? x[i0 + 1] : 0.0f;
            *(float2*)&xs[XP(2 * q2)] = v;
        }
    }
}

// Persistent kernel; 4 independent 96-thread groups per CTA (one warp per
// phase each), private double-buffered tiles, NO block-wide barrier in the
// steady state (only 3-warp named barriers).
// out[j] = sum_m x[m]*C[2j+32-3m], C[r] = sum_s b[s]*h[r-2s] (r in [0,163)).
// Group tile T: j = 1536*T + g + 3*(16*ll + d), G0 = 1024*T - 46 (even).
// out = sum_v xs_log[32*ll + 2d + v] * D_g[v], D_g[v] = C[2g + 170 - 3v]
// (zero outside [0,162]); v in [2,60) -> 29 packed steps.
__global__ void __launch_bounds__(BLOCK_T, 2) fused_kernel(
    const float* __restrict__ x, const float* __restrict__ h,
    const float* __restrict__ b, float* __restrict__ out,
    int n_in, int n_out, int out_total, int ntiles)
{
    extern __shared__ float smem[];

    int tid = threadIdx.x;
    int bx = blockIdx.x;
    int a = tid / 96;               // group 0..3
    int t96 = tid % 96;
    int g = t96 >> 5;               // phase 0..2 (one warp per phase)
    int ll = t96 & 31;

    float* xs0 = smem + (2 * a + 0) * XS_G;
    float* xs1 = smem + (2 * a + 1) * XS_G;
    float* og  = smem + 8 * XS_G + a * OS_G;
    unsigned long long* cs = (unsigned long long*)(smem + SMEM_FLOATS);

    int NG = (int)gridDim.x * 4;    // total groups
    int gid = bx * 4 + a;

    // --- prologue: prefetch this group's first tile immediately ---
    int T = gid;
    if (T < ntiles) fill_g(xs0, x, T, ntiles, n_in, t96);
    asm volatile("cp.async.commit_group;\n" ::: "memory");

    // --- coefficients: ONCE per block ---
    // cs[gg*NSTEP+t] = (D_gg[2+2t], D_gg[3+2t]) = (C[2gg+164-6t], C[2gg+161-6t])
    if (tid < 3 * NSTEP) {
        int gg = tid / NSTEP, t = tid % NSTEP;
        float hv[2];
        #pragma unroll
        for (int qq = 0; qq < 2; qq++) {
            int idx = 2 * gg + 164 - 6 * t - 3 * qq;   // C index
            float val = 0.0f;
            if (idx >= 0 && idx <= 162) {
                #pragma unroll
                for (int s = 0; s < 51; s++) {
                    int hh = idx - 2 * s;
                    if (hh >= 0 && hh < 63) val = fmaf(__ldg(&b[s]), __ldg(&h[hh]), val);
                }
            }
            hv[qq] = val;
        }
        cs[tid] =
            (unsigned long long)__float_as_uint(hv[0]) |
            ((unsigned long long)__float_as_uint(hv[1]) << 32);
    }
    __syncthreads();   // cs published; the ONLY block-wide barrier

    const unsigned long long* cp_ = cs + g * NSTEP;

    int cur = 0;
    for (; T < ntiles; T += NG, cur ^= 1) {
        // prefetch next tile into the spare buffer (its last readers finished
        // before the previous iteration's staging bar96)
        int Tn = T + NG;
        if (Tn < ntiles) fill_g(cur ? xs0 : xs1, x, Tn, ntiles, n_in, t96);
        asm volatile("cp.async.commit_group;\n" ::: "memory");
        asm volatile("cp.async.wait_group 1;\n" ::: "memory");   // tile T ready (this thread)
        asm volatile("bar.sync %0, 96;" :: "r"(a + 1) : "memory"); // ready for all 96

        const float* xb = (cur ? xs1 : xs0) + 34 * ll;

        // circular packed window: slot k = {xs_log[32ll+2+2k], xs_log[32ll+3+2k]}
        unsigned long long w2[16];
        #pragma unroll
        for (int k = 0; k < 16; k++)
            w2[k] = *(const unsigned long long*)&xb[XPOFF(2 + 2 * k)];

        unsigned long long acc2[R_OUT];
        #pragma unroll
        for (int d = 0; d < R_OUT; d++) acc2[d] = 0ull;

        #pragma unroll
        for (int t = 0; t < NSTEP; t++) {
            unsigned long long c = cp_[t];
            #pragma unroll
            for (int d = 0; d < R_OUT; d++)
                acc2[d] = fma_f32x2(w2[(t + d) & 15], c, acc2[d]);
            if (t < NSTEP - 1)
                w2[t & 15] = *(const unsigned long long*)&xb[XPOFF(2 + 2 * (t + 16))];
        }

        // --- group-local staging: logical oo = 48*ll + (g+3d), phys 49*ll + g + 3d ---
        #pragma unroll
        for (int d = 0; d < R_OUT; d++) {
            float lo = __uint_as_float((unsigned)(acc2[d] & 0xffffffffull));
            float hi = __uint_as_float((unsigned)(acc2[d] >> 32));
            og[49 * ll + g + 3 * d] = lo + hi;
        }
        asm volatile("bar.sync %0, 96;" :: "r"(a + 1) : "memory");

        // --- group-local coalesced writeback (1536 outputs) ---
        int jgrp = T * GT_OUT;
        if (jgrp >= 50 && jgrp + GT_OUT <= n_out) {
            #pragma unroll
            for (int it = 0; it < 4; it++) {
                int q4 = 4 * t96 + 384 * it;
                int ph = q4 + q4 / 48;
                float4 v;
                v.x = og[ph];
                v.y = og[ph + 1];
                v.z = og[ph + 2];
                v.w = og[ph + 3];
                *(float4*)&out[jgrp + q4] = v;
            }
        } else {
            for (int q = t96; q < GT_OUT; q += 96) {
                int j = jgrp + q;
                // j >= 50 (head handled exactly below) and j < n_out
                if ((unsigned)(j - 50) < (unsigned)(n_out - 50)) out[j] = og[q + q / 48];
            }
        }
    }

    // --- block 0: exact edge outputs (head + tail) ---
    if (bx == 0) {
        int n_tail = out_total - n_out;
        if (tid < 50 + n_tail) {
            long long j = (tid < 50) ? (long long)tid
                                     : (long long)n_out + (tid - 50);
            out[j] = edge_value(x, h, b, j, n_in, (long long)n_out);
        }
    }
}

extern "C" void kernel_launch(void* const* d_in, const int* in_sizes, int n_in_arrs,
                              void* d_out, int out_size) {
    const float* x = (const float*)d_in[0];
    const float* h = (const float*)d_in[1];
    const float* b = (const float*)d_in[2];
    float* out = (float*)d_out;

    int n_in = in_sizes[0];  // 8 * 1048576 = 8388608
    long long n3 = (long long)n_in * 3;
    long long n_out = n3 / 2 + ((n3 % 2) ? 1 : 0);  // 12582912
    int out_total = out_size;                        // 12583008
    int ntiles = (int)((n_out + GT_OUT - 1) / GT_OUT);  // 8192

    // Dynamic smem above 48KB needs the attribute; host-side, idempotent,
    // not a stream op (safe under graph capture).
    cudaFuncSetAttribute(fused_kernel,
                         cudaFuncAttributeMaxDynamicSharedMemorySize, SMEM_BYTES);

    int grid = NBLK;
    fused_kernel<<<grid, BLOCK_T, SMEM_BYTES>>>(
        x, h, b, out, n_in, (int)n_out, out_total, ntiles);
}